// round 6
// baseline (speedup 1.0000x reference)
#include <cuda_runtime.h>

#define NCO     513
#define NPAIRS  256
#define STEP    512
#define HOPS    16
#define CHUNKS  8
#define PI_F    3.14159265358979323846f

// ---- persistent device scratch ----
__device__ float g_u[NPAIRS * NCO];      // (|amp|+eps)*cos(sp) / 1024
__device__ float g_v[NPAIRS * NCO];      // (|amp|+eps)*sin(sp) / 1024
__device__ float g_d[NPAIRS * NCO];      // decay magnitude d
__device__ float g_d4[NPAIRS * NCO];     // d^4
__device__ float g_C1r[NPAIRS * 512];    // Z[k] = w[k]*C1[k] + w[512-k]*C2[k]
__device__ float g_C1i[NPAIRS * 512];
__device__ float g_C2r[NPAIRS * 512];
__device__ float g_C2i[NPAIRS * 512];

// ---------------------------------------------------------------------------
__global__ void init_base_kernel(const float* __restrict__ amp,
                                 const float* __restrict__ phase,
                                 const float* __restrict__ decay) {
    int idx = blockIdx.x * 256 + threadIdx.x;
    if (idx >= 64 * NCO * 4) return;
    int e  = idx & 3;
    int rk = idx >> 2;
    int k  = rk % NCO;
    int r  = rk / NCO;

    float a  = amp[idx];
    float ph = phase[idx];
    float dc = decay[idx];

    float d  = 0.5f + 0.45f / (1.0f + expf(-dc));   // BASE_RES + sigmoid*span*factor
    float sp = tanhf(ph) * PI_F;
    float m0 = fabsf(a) + 1e-12f;
    float sn, cs;
    sincosf(sp, &sn, &cs);

    const float sc = 1.0f / 1024.0f;                // fold irfft 1/N + pack /2
    int o = (r * 4 + e) * NCO + k;
    g_u[o] = m0 * cs * sc;
    g_v[o] = m0 * sn * sc;
    g_d[o] = d;
    float d2 = d * d;
    g_d4[o] = d2 * d2;
}

// fold irfft-unpack twiddle + conj symmetry into per-(pair,k) coeff planes
__global__ void init_pack_kernel() {
    int idx = blockIdx.x * 256 + threadIdx.x;       // 256*512
    if (idx >= NPAIRS * 512) return;
    int k    = idx & 511;
    int pair = idx >> 9;
    const float* U = g_u + pair * NCO;
    const float* V = g_v + pair * NCO;
    float c1r, c1i, c2r, c2i;
    if (k == 0) {
        c1r = U[0];  c1i = U[0];
        c2r = U[512]; c2i = -U[512];                // imag parts dropped (halfcomplex)
    } else {
        int q = 512 - k;
        float ty, tx;
        sincospif(k * (1.0f / 512.0f), &ty, &tx);   // e^{+2pi i k/1024}
        float suk = U[k], svk = V[k], suq = U[q], svq = V[q];
        c1r =  suk * (1.0f - ty) - tx * svk;
        c1i =  svk * (1.0f - ty) + tx * suk;
        c2r =  suq * (1.0f + ty) - tx * svq;
        c2i = -svq * (1.0f + ty) - tx * suq;
    }
    g_C1r[idx] = c1r; g_C1i[idx] = c1i;
    g_C2r[idx] = c2r; g_C2i[idx] = c2i;
}

// ---------------------------------------------------------------------------
__device__ __forceinline__ float2 cmul(float2 a, float2 b) {
    return make_float2(a.x * b.x - a.y * b.y, a.x * b.y + a.y * b.x);
}
__device__ __forceinline__ float2 cadd(float2 a, float2 b) {
    return make_float2(a.x + b.x, a.y + b.y);
}
__device__ __forceinline__ float2 csub(float2 a, float2 b) {
    return make_float2(a.x - b.x, a.y - b.y);
}

// natural-order inverse DFT-8 (kernel e^{+2pi i j r/8}) on registers
__device__ __forceinline__ void fft8(float2* a) {
    const float RH = 0.70710678118654752440f;
    float2 t0 = cadd(a[0], a[4]), t1 = csub(a[0], a[4]);
    float2 t2 = cadd(a[2], a[6]), t3 = csub(a[2], a[6]);
    float2 E0 = cadd(t0, t2), E2 = csub(t0, t2);
    float2 E1 = make_float2(t1.x - t3.y, t1.y + t3.x);
    float2 E3 = make_float2(t1.x + t3.y, t1.y - t3.x);
    float2 s0 = cadd(a[1], a[5]), s1 = csub(a[1], a[5]);
    float2 s2 = cadd(a[3], a[7]), s3 = csub(a[3], a[7]);
    float2 O0 = cadd(s0, s2), O2 = csub(s0, s2);
    float2 O1 = make_float2(s1.x - s3.y, s1.y + s3.x);
    float2 O3 = make_float2(s1.x + s3.y, s1.y - s3.x);
    float2 W1 = make_float2((O1.x - O1.y) * RH, (O1.x + O1.y) * RH);
    float2 W2 = make_float2(-O2.y, O2.x);
    float2 W3 = make_float2(-(O3.x + O3.y) * RH, (O3.x - O3.y) * RH);
    a[0] = cadd(E0, O0);  a[4] = csub(E0, O0);
    a[1] = cadd(E1, W1);  a[5] = csub(E1, W1);
    a[2] = cadd(E2, W2);  a[6] = csub(E2, W2);
    a[3] = cadd(E3, W3);  a[7] = csub(E3, W3);
}

__device__ __forceinline__ void gbar(int g) {
    asm volatile("bar.sync %0, %1;" :: "r"(g + 1), "r"(64) : "memory");
}

// ---------------------------------------------------------------------------
// One block = (pair, 16-hop chunk); 4 groups x 64 threads, 4 frames / iter.
// Radix-8 Stockham register-resident; coeffs+twiddles in smem; window in regs.
// ---------------------------------------------------------------------------
__global__ __launch_bounds__(256, 3) void synth_kernel(float* __restrict__ out) {
    __shared__ float  e4s[NCO];        // d^4 per bin
    __shared__ float  xre[4][528];     // exchange (re), padded
    __shared__ float  xim[4][528];     // exchange (im)
    __shared__ float2 cring[6][256];   // overlap-add carry ring
    __shared__ float2 stws1[7][64];    // stage-1 twiddles e^{2pi i (j+1)t/512}
    __shared__ float2 stws2[7][8];     // stage-2 twiddles e^{2pi i (j+1)p/64}
    __shared__ float  sC1r[512], sC1i[512], sC2r[512], sC2i[512];

    const int tid   = threadIdx.x;
    const int g     = tid >> 6;        // frame group 0..3
    const int t     = tid & 63;        // lane within group
    const int pair  = blockIdx.x;
    const int chunk = blockIdx.y;
    const int h0    = chunk * HOPS;
    const int f0    = chunk ? (h0 - 1) : 0;
    const int fmax  = h0 + HOPS - 1;
    const int NIT   = chunk ? 5 : 4;

    // ---- block prologue: fill shared tables ----
    for (int i = tid; i < NCO; i += 256) e4s[i] = g_d4[pair * NCO + i];
    {
        const int cb = pair * 512;
        for (int i = tid; i < 512; i += 256) {
            sC1r[i] = g_C1r[cb + i];
            sC1i[i] = g_C1i[cb + i];
            sC2r[i] = g_C2r[cb + i];
            sC2i[i] = g_C2i[cb + i];
        }
    }
    for (int i = tid; i < 448; i += 256) {
        int j  = i >> 6;               // 0..6  (twiddle exponent j+1)
        int tt = i & 63;
        float s, c;
        sincospif((float)((j + 1) * tt) * (1.0f / 256.0f), &s, &c);
        stws1[j][tt] = make_float2(c, s);
    }
    if (tid < 56) {
        int j = tid >> 3, pp = tid & 7;
        float s, c;
        sincospif((float)((j + 1) * pp) * (1.0f / 32.0f), &s, &c);
        stws2[j][pp] = make_float2(c, s);
    }
    cring[0][tid] = make_float2(0.0f, 0.0f);

    // ---- per-thread persistent registers ----
    float  wk[8], wq[8];
    float2 wA[8];                      // Hann pairs (win[2n], win[2n+1]), n = t+64j
    {
        const int   fs  = f0 + g;
        const float fsf = (float)fs;
        #pragma unroll
        for (int r = 0; r < 8; ++r) {
            int k = t + 64 * r;
            int q = 512 - k;
            float dk = g_d[pair * NCO + k];
            float dq = g_d[pair * NCO + q];
            float a = exp2f(fsf * log2f(dk));               // d^fs
            float b = exp2f(fsf * log2f(dq));
            if ((fs & 1) && (k & 1)) { a = -a; b = -b; }    // (-1)^{fs*k}
            wk[r] = a; wq[r] = b;
        }
        #pragma unroll
        for (int j = 0; j < 8; ++j) {
            int n = t + 64 * j;
            wA[j].x = 0.5f - 0.5f * cospif((float)n * (1.0f / 256.0f));
            wA[j].y = 0.5f - 0.5f * cospif((float)(2 * n + 1) * (1.0f / 512.0f));
        }
    }
    __syncthreads();

    float* myre = xre[g];
    float* myim = xim[g];
    float* outp = out + (size_t)pair * 65536;

    for (int it = 0; it < NIT; ++it) {
        const int  frame = f0 + 4 * it + g;
        const bool valid = (frame <= fmax);
        float2 a[8];

        if (valid) {
            // ---- build spectrum: Z[k] = wk*C1 + wq*C2 (coeffs from smem) ----
            #pragma unroll
            for (int r = 0; r < 8; ++r) {
                int k = t + 64 * r;
                a[r].x = wk[r] * sC1r[k] + wq[r] * sC2r[k];
                a[r].y = wk[r] * sC1i[k] + wq[r] * sC2i[k];
            }

            // ---- stage 1 (s=1) ----
            fft8(a);
            #pragma unroll
            for (int j = 1; j < 8; ++j) a[j] = cmul(a[j], stws1[j - 1][t]);
            #pragma unroll
            for (int j = 0; j < 8; ++j) {            // write x = 8t+j, pad32
                int x = 8 * t + j; int px = x + (x >> 5);
                myre[px] = a[j].x; myim[px] = a[j].y;
            }
            gbar(g);
            #pragma unroll
            for (int r = 0; r < 8; ++r) {            // read x = t+64r
                int x = t + 64 * r; int px = x + (x >> 5);
                a[r] = make_float2(myre[px], myim[px]);
            }

            // ---- stage 2 (s=8) ----
            fft8(a);
            {
                int p2 = t >> 3;
                #pragma unroll
                for (int j = 1; j < 8; ++j) a[j] = cmul(a[j], stws2[j - 1][p2]);
            }
            gbar(g);                                 // WAR: stage-1 reads done
            #pragma unroll
            for (int j = 0; j < 8; ++j) {            // write x = q+64p+8j, xor swizzle
                int x = (t & 7) + 64 * (t >> 3) + 8 * j;
                int sx = x ^ ((x >> 3) & 0x18);
                myre[sx] = a[j].x; myim[sx] = a[j].y;
            }
            gbar(g);
            #pragma unroll
            for (int r = 0; r < 8; ++r) {            // read x = t+64r
                int x = t + 64 * r;
                int sx = x ^ ((x >> 3) & 0x18);
                a[r] = make_float2(myre[sx], myim[sx]);
            }

            // ---- stage 3 (s=64): z[t+64j] in registers ----
            fft8(a);

            // ---- carry: windowed second half (j=4..7 -> n in [256,512)) ----
            int wslot = (4 * it + g + 1) % 6;
            #pragma unroll
            for (int j = 4; j < 8; ++j) {
                int n = t + 64 * j;
                cring[wslot][n - 256] =
                    make_float2(a[j].x * wA[j].x, a[j].y * wA[j].y);
            }
        }
        __syncthreads();

        if (valid && frame >= h0) {
            int rslot = (4 * it + g) % 6;
            #pragma unroll
            for (int j = 0; j < 4; ++j) {
                int n = t + 64 * j;
                float2 cv = cring[rslot][n];
                float2 o;
                o.x = a[j].x * wA[j].x + cv.x;
                o.y = a[j].y * wA[j].y + cv.y;
                *(float2*)(outp + (size_t)frame * STEP + 2 * n) = o;
            }
        }
        __syncthreads();

        // ---- advance decay by d^4 (sign invariant under f -> f+4) ----
        #pragma unroll
        for (int r = 0; r < 8; ++r) {
            int k = t + 64 * r;
            wk[r] *= e4s[k];
            wq[r] *= e4s[512 - k];
        }
    }
}

// ---------------------------------------------------------------------------
extern "C" void kernel_launch(void* const* d_in, const int* in_sizes, int n_in,
                              void* d_out, int out_size) {
    const float* amp   = (const float*)d_in[0];
    const float* phase = (const float*)d_in[1];
    const float* decay = (const float*)d_in[2];
    float* out = (float*)d_out;

    int total = 64 * NCO * 4;
    init_base_kernel<<<(total + 255) / 256, 256>>>(amp, phase, decay);
    init_pack_kernel<<<(NPAIRS * 512 + 255) / 256, 256>>>();

    dim3 grid(NPAIRS, CHUNKS);
    synth_kernel<<<grid, 256>>>(out);
}

// round 7
// speedup vs baseline: 1.3383x; 1.3383x over previous
#include <cuda_runtime.h>

#define NCO     513
#define NPAIRS  256
#define STEP    512
#define PI_F    3.14159265358979323846f

// ---- persistent device scratch ----
__device__ float  g_u[NPAIRS * NCO];     // (|amp|+eps)*cos(sp) / 1024
__device__ float  g_v[NPAIRS * NCO];     // (|amp|+eps)*sin(sp) / 1024
__device__ float  g_d[NPAIRS * NCO];     // decay magnitude d
__device__ float  g_e[NPAIRS * NCO];     // signed decay: (k odd ? -d : d)
__device__ float4 g_C[NPAIRS * 512];     // build coeffs (C1r,C1i,C2r,C2i)
__device__ float2 g_win2[512];           // Hann pairs (win[2n], win[2n+1])

// ---------------------------------------------------------------------------
__global__ void init_win_kernel() {
    int i = threadIdx.x;  // 0..511
    float w0 = 0.5f - 0.5f * cospif((2 * i    ) * (1.0f / 512.0f));
    float w1 = 0.5f - 0.5f * cospif((2 * i + 1) * (1.0f / 512.0f));
    g_win2[i] = make_float2(w0, w1);
}

__global__ void init_base_kernel(const float* __restrict__ amp,
                                 const float* __restrict__ phase,
                                 const float* __restrict__ decay) {
    int idx = blockIdx.x * 256 + threadIdx.x;
    if (idx >= 64 * NCO * 4) return;
    int e  = idx & 3;
    int rk = idx >> 2;
    int k  = rk % NCO;
    int r  = rk / NCO;

    float a  = amp[idx];
    float ph = phase[idx];
    float dc = decay[idx];

    float d  = 0.5f + 0.45f / (1.0f + expf(-dc));   // BASE_RES + sigmoid*span*factor
    float sp = tanhf(ph) * PI_F;
    float m0 = fabsf(a) + 1e-12f;
    float sn, cs;
    sincosf(sp, &sn, &cs);

    const float sc = 1.0f / 1024.0f;                // fold irfft 1/N + pack /2
    int o = (r * 4 + e) * NCO + k;
    g_u[o] = m0 * cs * sc;
    g_v[o] = m0 * sn * sc;
    g_d[o] = d;
    g_e[o] = (k & 1) ? -d : d;                      // folds (-1)^{f*k} per-frame sign
}

// Z[k] = w[k]*C1[k] + w[512-k]*C2[k]  (irfft-unpack twiddle folded in)
__global__ void init_pack_kernel() {
    int idx = blockIdx.x * 256 + threadIdx.x;       // 256*512
    if (idx >= NPAIRS * 512) return;
    int k    = idx & 511;
    int pair = idx >> 9;
    const float* U = g_u + pair * NCO;
    const float* V = g_v + pair * NCO;
    float4 c;
    if (k == 0) {
        c = make_float4(U[0], U[0], U[512], -U[512]);   // imag parts dropped
    } else {
        int q = 512 - k;
        float ty, tx;
        sincospif(k * (1.0f / 512.0f), &ty, &tx);   // e^{+2pi i k/1024}
        float suk = U[k], svk = V[k], suq = U[q], svq = V[q];
        c.x =  suk * (1.0f - ty) - tx * svk;
        c.y =  svk * (1.0f - ty) + tx * suk;
        c.z =  suq * (1.0f + ty) - tx * svq;
        c.w = -svq * (1.0f + ty) - tx * suq;
    }
    g_C[idx] = c;
}

// ---------------------------------------------------------------------------
__device__ __forceinline__ float2 cmul(float2 a, float2 b) {
    return make_float2(a.x * b.x - a.y * b.y, a.x * b.y + a.y * b.x);
}
__device__ __forceinline__ float2 cadd(float2 a, float2 b) {
    return make_float2(a.x + b.x, a.y + b.y);
}
__device__ __forceinline__ float2 csub(float2 a, float2 b) {
    return make_float2(a.x - b.x, a.y - b.y);
}

// natural-order inverse DFT-8 (kernel e^{+2pi i j r/8}) on registers
__device__ __forceinline__ void fft8(float2* a) {
    const float RH = 0.70710678118654752440f;
    float2 t0 = cadd(a[0], a[4]), t1 = csub(a[0], a[4]);
    float2 t2 = cadd(a[2], a[6]), t3 = csub(a[2], a[6]);
    float2 E0 = cadd(t0, t2), E2 = csub(t0, t2);
    float2 E1 = make_float2(t1.x - t3.y, t1.y + t3.x);
    float2 E3 = make_float2(t1.x + t3.y, t1.y - t3.x);
    float2 s0 = cadd(a[1], a[5]), s1 = csub(a[1], a[5]);
    float2 s2 = cadd(a[3], a[7]), s3 = csub(a[3], a[7]);
    float2 O0 = cadd(s0, s2), O2 = csub(s0, s2);
    float2 O1 = make_float2(s1.x - s3.y, s1.y + s3.x);
    float2 O3 = make_float2(s1.x + s3.y, s1.y - s3.x);
    float2 W1 = make_float2((O1.x - O1.y) * RH, (O1.x + O1.y) * RH);
    float2 W2 = make_float2(-O2.y, O2.x);
    float2 W3 = make_float2(-(O3.x + O3.y) * RH, (O3.x - O3.y) * RH);
    a[0] = cadd(E0, O0);  a[4] = csub(E0, O0);
    a[1] = cadd(E1, W1);  a[5] = csub(E1, W1);
    a[2] = cadd(E2, W2);  a[6] = csub(E2, W2);
    a[3] = cadd(E3, W3);  a[7] = csub(E3, W3);
}

__device__ __forceinline__ void gbar(int g) {
    asm volatile("bar.sync %0, %1;" :: "r"(g + 1), "r"(64) : "memory");
}

// ---------------------------------------------------------------------------
// One block = (pair, 32-hop chunk); 4 independent groups x 64 threads.
// Group g serially computes frames [chunk*32 + 8g .. +7] (+1 warm-up);
// overlap-add carry lives in registers. Double-buffered exchanges ->
// 2 named barriers per frame, zero block-wide syncs in the loop.
// ---------------------------------------------------------------------------
__global__ __launch_bounds__(256, 2) void synth_kernel(float* __restrict__ out) {
    __shared__ float  se1[NCO];        // signed per-frame decay
    __shared__ float  Are[4][528], Aim[4][528];   // stage-1 exchange (pad32)
    __shared__ float  Bre[4][528], Bim[4][528];   // stage-2 exchange (xor)
    __shared__ float2 winp[512];       // Hann pairs

    const int tid   = threadIdx.x;
    const int g     = tid >> 6;        // group 0..3
    const int t     = tid & 63;        // lane within group
    const int pair  = blockIdx.x;
    const int chunk = blockIdx.y;
    const int fstart = chunk * 32 + g * 8;
    const int f0     = fstart ? (fstart - 1) : 0;  // warm-up frame

    for (int i = tid; i < NCO; i += 256) se1[i] = g_e[pair * NCO + i];
    for (int i = tid; i < 512; i += 256) winp[i] = g_win2[i];
    __syncthreads();

    // ---- per-thread persistent registers ----
    float4 C[8];
    float  wk[8], wq[8];
    float2 tws1[8], tws2[8];
    {
        const float fsf = (float)f0;
        #pragma unroll
        for (int r = 0; r < 8; ++r) {
            int k = t + 64 * r;
            int q = 512 - k;
            C[r] = g_C[pair * 512 + k];
            float dk = g_d[pair * NCO + k];
            float dq = g_d[pair * NCO + q];
            float a = exp2f(fsf * log2f(dk));               // d^f0
            float b = exp2f(fsf * log2f(dq));
            if ((f0 & 1) && (k & 1)) { a = -a; b = -b; }    // (-1)^{f0*k}
            wk[r] = a; wq[r] = b;
        }
        int p2 = t >> 3;
        #pragma unroll
        for (int j = 1; j < 8; ++j) {
            float s, c;
            sincospif((float)(j * t) * (1.0f / 256.0f), &s, &c);   // e^{2pi i jt/512}
            tws1[j] = make_float2(c, s);
            float s2, c2;
            sincospif((float)(j * p2) * (1.0f / 32.0f), &s2, &c2); // e^{2pi i j(t>>3)/64}
            tws2[j] = make_float2(c2, s2);
        }
    }

    float2 carry[4];
    #pragma unroll
    for (int j = 0; j < 4; ++j) carry[j] = make_float2(0.0f, 0.0f);

    float* ar = Are[g]; float* ai = Aim[g];
    float* br = Bre[g]; float* bi = Bim[g];
    float* outp = out + (size_t)pair * 65536;

    const int fend = fstart + 8;
    for (int f = f0; f < fend; ++f) {
        float2 a[8];

        // ---- build spectrum: Z[k] = wk*C1 + wq*C2 ----
        #pragma unroll
        for (int r = 0; r < 8; ++r) {
            a[r].x = wk[r] * C[r].x + wq[r] * C[r].z;
            a[r].y = wk[r] * C[r].y + wq[r] * C[r].w;
        }

        // ---- stage 1 (s=1): buffer A, pad32 ----
        fft8(a);
        #pragma unroll
        for (int j = 1; j < 8; ++j) a[j] = cmul(a[j], tws1[j]);
        #pragma unroll
        for (int j = 0; j < 8; ++j) {            // write x = 8t+j
            int x = 8 * t + j; int px = x + (x >> 5);
            ar[px] = a[j].x; ai[px] = a[j].y;
        }
        gbar(g);
        #pragma unroll
        for (int r = 0; r < 8; ++r) {            // read x = t+64r
            int x = t + 64 * r; int px = x + (x >> 5);
            a[r] = make_float2(ar[px], ai[px]);
        }

        // ---- stage 2 (s=8): buffer B, xor swizzle ----
        fft8(a);
        {
            int p2 = t >> 3;
            #pragma unroll
            for (int j = 1; j < 8; ++j) a[j] = cmul(a[j], tws2[j]);
        }
        #pragma unroll
        for (int j = 0; j < 8; ++j) {            // write x = q+64p+8j
            int x = (t & 7) + 64 * (t >> 3) + 8 * j;
            int sx = x ^ ((x >> 3) & 0x18);
            br[sx] = a[j].x; bi[sx] = a[j].y;
        }
        gbar(g);
        #pragma unroll
        for (int r = 0; r < 8; ++r) {            // read x = t+64r
            int x = t + 64 * r;
            int sx = x ^ ((x >> 3) & 0x18);
            a[r] = make_float2(br[sx], bi[sx]);
        }

        // ---- stage 3 (s=64): z[t+64j] in registers ----
        fft8(a);

        // ---- window + overlap-add (carry in registers) ----
        if (f >= fstart) {
            #pragma unroll
            for (int j = 0; j < 4; ++j) {
                int n = t + 64 * j;
                float2 wv = winp[n];
                float2 o;
                o.x = a[j].x * wv.x + carry[j].x;
                o.y = a[j].y * wv.y + carry[j].y;
                *(float2*)(outp + (size_t)f * STEP + 2 * n) = o;
            }
        }
        #pragma unroll
        for (int j = 0; j < 4; ++j) {
            int n = t + 64 * (j + 4);
            float2 wv = winp[n];
            carry[j] = make_float2(a[j + 4].x * wv.x, a[j + 4].y * wv.y);
        }

        // ---- advance decay one frame (sign folded into se1) ----
        #pragma unroll
        for (int r = 0; r < 8; ++r) {
            int k = t + 64 * r;
            wk[r] *= se1[k];
            wq[r] *= se1[512 - k];
        }
    }
}

// ---------------------------------------------------------------------------
extern "C" void kernel_launch(void* const* d_in, const int* in_sizes, int n_in,
                              void* d_out, int out_size) {
    const float* amp   = (const float*)d_in[0];
    const float* phase = (const float*)d_in[1];
    const float* decay = (const float*)d_in[2];
    float* out = (float*)d_out;

    init_win_kernel<<<1, 512>>>();
    int total = 64 * NCO * 4;
    init_base_kernel<<<(total + 255) / 256, 256>>>(amp, phase, decay);
    init_pack_kernel<<<(NPAIRS * 512 + 255) / 256, 256>>>();

    dim3 grid(NPAIRS, 4);
    synth_kernel<<<grid, 256>>>(out);
}